// round 5
// baseline (speedup 1.0000x reference)
#include <cuda_runtime.h>
#include <math.h>

#define DIMV 32
#define KN 16
#define NREL 60
#define NT 256
#define WPB 8   // warps (batch elements) per block

__device__ __forceinline__ float sigm(float x) { return 1.f / (1.f + __expf(-x)); }

__device__ __forceinline__ float softmax16(float sc) {
    float m = sc;
    #pragma unroll
    for (int o = 8; o > 0; o >>= 1) m = fmaxf(m, __shfl_xor_sync(0xffffffffu, m, o, 16));
    float e = __expf(sc - m);
    float s = e;
    #pragma unroll
    for (int o = 8; o > 0; o >>= 1) s += __shfl_xor_sync(0xffffffffu, s, o, 16);
    return e / s;
}

__device__ __forceinline__ float udr_lookup(float u0, float u1, int rid) {
    float a = __shfl_sync(0xffffffffu, u0, rid & 31);
    float b = __shfl_sync(0xffffffffu, u1, rid & 31);
    return (rid < 32) ? a : b;
}

__global__ __launch_bounds__(NT, 5) void mkgcn_kernel(
    const int*   __restrict__ users,
    const int*   __restrict__ items,
    const float* __restrict__ emb,
    const float* __restrict__ rel,
    const int*   __restrict__ adjE,
    const int*   __restrict__ adjR,
    const int*   __restrict__ hist,
    const float* __restrict__ W,
    const float* __restrict__ bvec,
    float*       __restrict__ out,
    int B)
{
    __shared__ float Ws[DIMV * DIMV];
    __shared__ float bs[DIMV];
    __shared__ float rels[NREL * DIMV];          // bank-swizzled: [r*32 + ((d+r)&31)]
    __shared__ float xs[WPB][KN][DIMV];          // e1 -> x -> t1, in place
    __shared__ int   ids_s[WPB][KN][KN];
    __shared__ float at_s [WPB][KN][KN];

    const int tid  = threadIdx.x;
    const int w    = tid >> 5;
    const int lane = tid & 31;

    // ---- block-wide staging ----
    #pragma unroll
    for (int i = tid; i < DIMV * DIMV; i += NT) Ws[i] = __ldg(&W[i]);
    if (tid < DIMV) bs[tid] = __ldg(&bvec[tid]);
    #pragma unroll
    for (int i = tid; i < NREL * DIMV; i += NT) {
        int r = i >> 5, d = i & 31;
        rels[r * DIMV + ((d + r) & 31)] = __ldg(&rel[i]);
    }
    __syncthreads();

    const int b = blockIdx.x * WPB + w;
    if (b >= B) return;

    // W column for this lane, kept in registers (reused by 18 matvecs)
    float Wcol[DIMV];
    #pragma unroll
    for (int j = 0; j < DIMV; ++j) Wcol[j] = Ws[j * DIMV + lane];
    const float bl = bs[lane];

    const int uid  = __ldg(&users[b]);
    const int item = __ldg(&items[b]);

    // ---- independent front loads ----
    const float e0 = __ldg(&emb[(size_t)item * DIMV + lane]);
    const int   hid = __ldg(&hist[(size_t)uid * KN + (lane & 15)]);
    const int   e1  = __ldg(&adjE[(size_t)item * KN + (lane & 15)]);
    const int   r0  = __ldg(&adjR[(size_t)item * KN + (lane & 15)]);

    // ---- user embedding: 16 independent row gathers ----
    float us = 0.f;
    #pragma unroll
    for (int k = 0; k < KN; ++k) {
        int id = __shfl_sync(0xffffffffu, hid, k);
        us += __ldg(&emb[(size_t)id * DIMV + lane]);
    }
    const float uemb = us * (1.f / 16.f);

    // ---- udotr[0..59]: lane r holds u0 = udotr[r], u1 = udotr[r+32] ----
    float u0 = 0.f, u1 = 0.f;
    const int r2 = lane + 32;
    #pragma unroll
    for (int d = 0; d < DIMV; ++d) {
        float ud = __shfl_sync(0xffffffffu, uemb, d);
        u0 += ud * rels[lane * DIMV + ((d + lane) & 31)];
        if (r2 < NREL) u1 += ud * rels[r2 * DIMV + ((d + r2) & 31)];
    }

    // ---- hop-0 attention (halves duplicate; width-16 softmax) ----
    const float a0 = softmax16(udr_lookup(u0, u1, r0));

    // ---- hop-2 adjacency + hop-1 attention into per-warp shared ----
    #pragma unroll
    for (int p = 0; p < 8; ++p) {
        int row  = 2 * p + (lane >> 4);
        int base = __shfl_sync(0xffffffffu, e1, row);
        int k    = lane & 15;
        int id   = __ldg(&adjE[(size_t)base * KN + k]);
        int rid  = __ldg(&adjR[(size_t)base * KN + k]);
        float a  = softmax16(udr_lookup(u0, u1, rid));
        ids_s[w][row][k] = id;
        at_s [w][row][k] = a;
    }

    // ---- e1 gather: fill xs rows + hop-0 aggregate in registers ----
    float acc0 = 0.f;
    #pragma unroll
    for (int k = 0; k < KN; ++k) {
        int id  = __shfl_sync(0xffffffffu, e1, k);
        float v = __ldg(&emb[(size_t)id * DIMV + lane]);
        acc0 += __shfl_sync(0xffffffffu, a0, k) * v;
        xs[w][k][lane] = v;
    }
    __syncwarp();

    // ---- hop-2 gather: 256 independent single-line LDGs ----
    #pragma unroll 2
    for (int n = 0; n < KN; ++n) {
        float agg = 0.f;
        #pragma unroll
        for (int k = 0; k < KN; ++k) {
            int   id = ids_s[w][n][k];
            float a  = at_s [w][n][k];
            agg += a * __ldg(&emb[(size_t)id * DIMV + lane]);
        }
        xs[w][n][lane] += agg;      // x = e1 + agg
    }
    __syncwarp();

    // ---- 16 hop-1 matvecs; t1 overwrites x in place ----
    #pragma unroll 1
    for (int n = 0; n < KN; ++n) {
        float y = bl;
        #pragma unroll
        for (int j = 0; j < DIMV; ++j)
            y += xs[w][n][j] * Wcol[j];
        __syncwarp();
        xs[w][n][lane] = sigm(y);
        __syncwarp();
    }

    // ---- hop-0 matvec (shuffle-based; xs rows are occupied by t1) ----
    float x0 = e0 + acc0;
    float y0 = bl;
    #pragma unroll
    for (int j = 0; j < DIMV; ++j)
        y0 += __shfl_sync(0xffffffffu, x0, j) * Wcol[j];
    float t0 = sigm(y0);

    // ---- final aggregate + matvec + score ----
    float accf = 0.f;
    #pragma unroll
    for (int k = 0; k < KN; ++k)
        accf += __shfl_sync(0xffffffffu, a0, k) * xs[w][k][lane];
    float xf = t0 + accf;
    float yf = bl;
    #pragma unroll
    for (int j = 0; j < DIMV; ++j)
        yf += __shfl_sync(0xffffffffu, xf, j) * Wcol[j];
    float f = tanhf(yf);

    float s = uemb * f;
    #pragma unroll
    for (int o = 16; o > 0; o >>= 1) s += __shfl_xor_sync(0xffffffffu, s, o);
    if (lane == 0) out[b] = sigm(s);
}

extern "C" void kernel_launch(void* const* d_in, const int* in_sizes, int n_in,
                              void* d_out, int out_size) {
    const int*   users        = (const int*)  d_in[0];
    const int*   items        = (const int*)  d_in[1];
    const float* entity_emb   = (const float*)d_in[2];
    const float* relation_emb = (const float*)d_in[3];
    const int*   adj_entity   = (const int*)  d_in[4];
    const int*   adj_relation = (const int*)  d_in[5];
    const int*   user_history = (const int*)  d_in[6];
    const float* W            = (const float*)d_in[7];
    const float* b            = (const float*)d_in[8];
    float* out = (float*)d_out;

    int B = in_sizes[0];
    int grid = (B + WPB - 1) / WPB;
    mkgcn_kernel<<<grid, NT>>>(users, items, entity_emb, relation_emb,
                               adj_entity, adj_relation, user_history,
                               W, b, out, B);
}

// round 6
// speedup vs baseline: 1.3838x; 1.3838x over previous
#include <cuda_runtime.h>
#include <math.h>

#define DIMV 32
#define KN 16
#define NREL 60
#define MAXB 8192
#define NTASK 17   // 16 hop-1 nodes + 1 hop-0 node per element

// scratch (device globals)
__device__ float g_uemb [MAXB * DIMV];
__device__ int   g_e1id [MAXB * KN];
__device__ float g_attn0[MAXB * KN];
__device__ int   g_e2id [MAXB * KN * KN];
__device__ float g_attn1[MAXB * KN * KN];
__device__ float g_t    [MAXB * NTASK * DIMV];

__device__ __forceinline__ float sigm(float x) { return 1.f / (1.f + __expf(-x)); }

__device__ __forceinline__ float softmax16(float sc) {
    float m = sc;
    #pragma unroll
    for (int o = 8; o > 0; o >>= 1) m = fmaxf(m, __shfl_xor_sync(0xffffffffu, m, o, 16));
    float e = __expf(sc - m);
    float s = e;
    #pragma unroll
    for (int o = 8; o > 0; o >>= 1) s += __shfl_xor_sync(0xffffffffu, s, o, 16);
    return e / s;
}

__device__ __forceinline__ float udr_lookup(float u0, float u1, int rid) {
    float a = __shfl_sync(0xffffffffu, u0, rid & 31);
    float b = __shfl_sync(0xffffffffu, u1, rid & 31);
    return (rid < 32) ? a : b;
}

// ---- KA: warp per element. ids, uemb, udotr, attention weights. ----------
__global__ __launch_bounds__(256) void ka_kernel(
    const int*   __restrict__ users,
    const int*   __restrict__ items,
    const float* __restrict__ emb,
    const float* __restrict__ rel,
    const int*   __restrict__ adjE,
    const int*   __restrict__ adjR,
    const int*   __restrict__ hist,
    int B)
{
    __shared__ float rels[NREL * DIMV];   // swizzled [r*32 + ((d+r)&31)]

    const int tid = threadIdx.x, lane = tid & 31, w = tid >> 5;
    #pragma unroll
    for (int i = tid; i < NREL * DIMV; i += 256) {
        int r = i >> 5, d = i & 31;
        rels[r * DIMV + ((d + r) & 31)] = __ldg(&rel[i]);
    }
    __syncthreads();

    const int b = blockIdx.x * 8 + w;
    if (b >= B) return;

    const int uid  = __ldg(&users[b]);
    const int item = __ldg(&items[b]);
    const int kl   = lane & 15;

    const int hid = __ldg(&hist[(size_t)uid  * KN + kl]);
    const int e1  = __ldg(&adjE[(size_t)item * KN + kl]);
    const int r0  = __ldg(&adjR[(size_t)item * KN + kl]);

    // user embedding
    float us = 0.f;
    #pragma unroll
    for (int k = 0; k < KN; ++k) {
        int id = __shfl_sync(0xffffffffu, hid, k);
        us += __ldg(&emb[(size_t)id * DIMV + lane]);
    }
    const float uemb = us * (1.f / 16.f);
    g_uemb[b * DIMV + lane] = uemb;

    // udotr: lane r holds udotr[r] (u0) and udotr[r+32] (u1)
    float u0 = 0.f, u1 = 0.f;
    const int r2 = lane + 32;
    #pragma unroll
    for (int d = 0; d < DIMV; ++d) {
        float ud = __shfl_sync(0xffffffffu, uemb, d);
        u0 += ud * rels[lane * DIMV + ((d + lane) & 31)];
        if (r2 < NREL) u1 += ud * rels[r2 * DIMV + ((d + r2) & 31)];
    }

    // hop-0 attention + e1 ids
    float a0 = softmax16(udr_lookup(u0, u1, r0));
    if (lane < KN) {
        g_e1id [b * KN + lane] = e1;
        g_attn0[b * KN + lane] = a0;
    }

    // hop-2 adjacency + hop-1 attention: 8 iters x (2 rows x 16 cols)
    #pragma unroll
    for (int p = 0; p < 8; ++p) {
        int row  = 2 * p + (lane >> 4);
        int base = __shfl_sync(0xffffffffu, e1, row);
        int id   = __ldg(&adjE[(size_t)base * KN + kl]);
        int rid  = __ldg(&adjR[(size_t)base * KN + kl]);
        float a  = softmax16(udr_lookup(u0, u1, rid));
        size_t o = (size_t)b * 256 + row * KN + kl;
        g_e2id [o] = id;
        g_attn1[o] = a;
    }
}

// ---- KB: warp per (element, task). 17 gathers + shuffle matvec. ----------
__global__ __launch_bounds__(256, 8) void kb_kernel(
    const int*   __restrict__ items,
    const float* __restrict__ emb,
    const float* __restrict__ W,
    const float* __restrict__ bvec,
    int B)
{
    __shared__ float Ws[DIMV * DIMV];
    __shared__ float bs[DIMV];
    const int tid = threadIdx.x, lane = tid & 31, w = tid >> 5;
    #pragma unroll
    for (int i = tid; i < DIMV * DIMV; i += 256) Ws[i] = __ldg(&W[i]);
    if (tid < DIMV) bs[tid] = __ldg(&bvec[tid]);
    __syncthreads();

    const int task = blockIdx.x * 8 + w;
    const int b = task / NTASK;
    const int t = task - b * NTASK;
    if (b >= B) return;

    int   id  = 0;
    float wgt = 0.f;
    int   selfid;
    if (t < KN) {
        if (lane < KN) {
            size_t o = (size_t)b * 256 + t * KN + lane;
            id  = __ldg(&g_e2id [o]);
            wgt = __ldg(&g_attn1[o]);
        }
        selfid = __ldg(&g_e1id[b * KN + t]);
    } else {
        if (lane < KN) {
            id  = __ldg(&g_e1id [b * KN + lane]);
            wgt = __ldg(&g_attn0[b * KN + lane]);
        }
        selfid = __ldg(&items[b]);
    }

    float x = __ldg(&emb[(size_t)selfid * DIMV + lane]);
    float acc = 0.f;
    #pragma unroll
    for (int k = 0; k < KN; ++k) {
        int   ik = __shfl_sync(0xffffffffu, id,  k);
        float wk = __shfl_sync(0xffffffffu, wgt, k);
        acc += wk * __ldg(&emb[(size_t)ik * DIMV + lane]);
    }
    x += acc;

    float y = bs[lane];
    #pragma unroll
    for (int j = 0; j < DIMV; ++j)
        y += __shfl_sync(0xffffffffu, x, j) * Ws[j * DIMV + lane];

    g_t[((size_t)b * NTASK + t) * DIMV + lane] = sigm(y);
}

// ---- KC: warp per element. Final matvec + score. -------------------------
__global__ __launch_bounds__(256, 8) void kc_kernel(
    const float* __restrict__ W,
    const float* __restrict__ bvec,
    float*       __restrict__ out,
    int B)
{
    __shared__ float Ws[DIMV * DIMV];
    __shared__ float bs[DIMV];
    const int tid = threadIdx.x, lane = tid & 31, w = tid >> 5;
    #pragma unroll
    for (int i = tid; i < DIMV * DIMV; i += 256) Ws[i] = __ldg(&W[i]);
    if (tid < DIMV) bs[tid] = __ldg(&bvec[tid]);
    __syncthreads();

    const int b = blockIdx.x * 8 + w;
    if (b >= B) return;

    float a0 = (lane < KN) ? __ldg(&g_attn0[b * KN + lane]) : 0.f;
    const float* tb = g_t + (size_t)b * NTASK * DIMV;

    float t0 = __ldg(&tb[16 * DIMV + lane]);
    float accf = 0.f;
    #pragma unroll
    for (int k = 0; k < KN; ++k) {
        float ak = __shfl_sync(0xffffffffu, a0, k);
        accf += ak * __ldg(&tb[k * DIMV + lane]);
    }
    float xf = t0 + accf;
    float yf = bs[lane];
    #pragma unroll
    for (int j = 0; j < DIMV; ++j)
        yf += __shfl_sync(0xffffffffu, xf, j) * Ws[j * DIMV + lane];
    float f = tanhf(yf);

    float s = __ldg(&g_uemb[b * DIMV + lane]) * f;
    #pragma unroll
    for (int o = 16; o > 0; o >>= 1) s += __shfl_xor_sync(0xffffffffu, s, o);
    if (lane == 0) out[b] = sigm(s);
}

extern "C" void kernel_launch(void* const* d_in, const int* in_sizes, int n_in,
                              void* d_out, int out_size) {
    const int*   users        = (const int*)  d_in[0];
    const int*   items        = (const int*)  d_in[1];
    const float* entity_emb   = (const float*)d_in[2];
    const float* relation_emb = (const float*)d_in[3];
    const int*   adj_entity   = (const int*)  d_in[4];
    const int*   adj_relation = (const int*)  d_in[5];
    const int*   user_history = (const int*)  d_in[6];
    const float* W            = (const float*)d_in[7];
    const float* b            = (const float*)d_in[8];
    float* out = (float*)d_out;

    int B = in_sizes[0];
    int gA = (B + 7) / 8;
    int gB = (B * NTASK + 7) / 8;
    int gC = (B + 7) / 8;
    ka_kernel<<<gA, 256>>>(users, items, entity_emb, relation_emb,
                           adj_entity, adj_relation, user_history, B);
    kb_kernel<<<gB, 256>>>(items, entity_emb, W, b, B);
    kc_kernel<<<gC, 256>>>(W, b, out, B);
}